// round 5
// baseline (speedup 1.0000x reference)
#include <cuda_runtime.h>

#define NUM_USERS 50000
#define NUM_ITEMS 100000
#define NUM_NODES 150000
#define D 64
#define NNZ_E 4800000
#define BATCH_B 4096

// Static scratch (no allocation allowed; BSS __device__ globals).
// x0 lives in g_x0; layer outputs ping among g_x1/g_x2:
//   layer1: x0 -> g_x1 (x1)
//   layer2: g_x1 -> g_x2 (x2)
//   layer3: g_x2 -> g_x1 with += (g_x1 ends as x1+x3)
__device__ float g_x0[(size_t)NUM_NODES * D];
__device__ float g_x1[(size_t)NUM_NODES * D];
__device__ float g_x2[(size_t)NUM_NODES * D];
__device__ int   g_rowptr[NUM_NODES + 1];

// ---------------------------------------------------------------------------
// Kernel 1: concat user/item embeddings into g_x0.
// NUM_USERS*D = 3.2M floats, divisible by 4 -> no float4 straddle.
// ---------------------------------------------------------------------------
__global__ void init_kernel(const float* __restrict__ user_emb,
                            const float* __restrict__ item_emb) {
    int i = blockIdx.x * blockDim.x + threadIdx.x;        // float4 index
    const int total4 = NUM_NODES * D / 4;                  // 2.4M
    if (i >= total4) return;
    const int user4 = NUM_USERS * D / 4;                   // 800k
    float4 v;
    if (i < user4) {
        v = *(const float4*)(user_emb + (size_t)i * 4);
    } else {
        v = *(const float4*)(item_emb + (size_t)(i - user4) * 4);
    }
    ((float4*)g_x0)[i] = v;
}

// ---------------------------------------------------------------------------
// Kernel 2: CSR row pointers via binary search over sorted edge_rows
// ---------------------------------------------------------------------------
__global__ void rowptr_kernel(const int* __restrict__ edge_rows) {
    int r = blockIdx.x * blockDim.x + threadIdx.x;
    if (r > NUM_NODES) return;
    int lo = 0, hi = NNZ_E;
    while (lo < hi) {
        int mid = (lo + hi) >> 1;
        if (__ldg(edge_rows + mid) < r) lo = mid + 1;
        else hi = mid;
    }
    g_rowptr[r] = lo;
}

// ---------------------------------------------------------------------------
// Kernel 3: SpMM, one warp per row, DUAL-EDGE gather:
//   lanes 0-15  gather edge (2t)  's row as float4 (features 4l..4l+3)
//   lanes 16-31 gather edge (2t+1)'s row as float4
// Per 2 edges: 1 LDG.128 + 2 SHFL (vs 2 LDG.64 + 4 SHFL before).
// Halves combined at the end with 4 shfl_xor(16); lanes 0-15 write float4.
// SRC/DST select among g_x0/g_x1/g_x2; ADD accumulates into DST.
// ---------------------------------------------------------------------------
template<int SRC, int DST, int ADD>
__global__ void __launch_bounds__(256)
spmm_kernel(const int*   __restrict__ edge_cols,
            const float* __restrict__ edge_vals) {
    const float* __restrict__ x = (SRC == 0) ? g_x0 : ((SRC == 1) ? g_x1 : g_x2);
    float*       __restrict__ y = (DST == 1) ? g_x1 : g_x2;

    int gw   = (blockIdx.x * blockDim.x + threadIdx.x) >> 5;
    int lane = threadIdx.x & 31;
    if (gw >= NUM_NODES) return;

    int beg = g_rowptr[gw];
    int end = g_rowptr[gw + 1];
    const int half = lane >> 4;              // 0: even edges, 1: odd edges
    const int fl   = (lane & 15) * 4;        // this lane's feature offset

    float4 a = make_float4(0.f, 0.f, 0.f, 0.f);

    int e = beg;
    for (; e + 32 <= end; e += 32) {
        int   c = __ldg(edge_cols + e + lane);
        float v = __ldg(edge_vals + e + lane);
        #pragma unroll
        for (int t = 0; t < 16; t++) {
            int   src = 2 * t + half;
            int   cj  = __shfl_sync(0xffffffffu, c, src);
            float vj  = __shfl_sync(0xffffffffu, v, src);
            float4 xv = *(const float4*)(x + (size_t)cj * D + fl);
            a.x = fmaf(vj, xv.x, a.x);
            a.y = fmaf(vj, xv.y, a.y);
            a.z = fmaf(vj, xv.z, a.z);
            a.w = fmaf(vj, xv.w, a.w);
        }
    }
    int n = end - e;
    if (n > 0) {
        int   c = 0; float v = 0.f;   // lanes >= n: v=0, c=0 -> gathers row 0 * 0
        if (lane < n) { c = __ldg(edge_cols + e + lane); v = __ldg(edge_vals + e + lane); }
        int iters = (n + 1) >> 1;
        for (int t = 0; t < iters; t++) {
            int   src = 2 * t + half;
            int   cj  = __shfl_sync(0xffffffffu, c, src);
            float vj  = __shfl_sync(0xffffffffu, v, src);
            float4 xv = *(const float4*)(x + (size_t)cj * D + fl);
            a.x = fmaf(vj, xv.x, a.x);
            a.y = fmaf(vj, xv.y, a.y);
            a.z = fmaf(vj, xv.z, a.z);
            a.w = fmaf(vj, xv.w, a.w);
        }
    }

    // Combine even-edge and odd-edge halves (lane l <-> lane l+16).
    a.x += __shfl_xor_sync(0xffffffffu, a.x, 16);
    a.y += __shfl_xor_sync(0xffffffffu, a.y, 16);
    a.z += __shfl_xor_sync(0xffffffffu, a.z, 16);
    a.w += __shfl_xor_sync(0xffffffffu, a.w, 16);

    if (half == 0) {
        size_t o = (size_t)gw * D + fl;
        if (ADD) {
            float4 p = *(const float4*)(y + o);
            a.x += p.x; a.y += p.y; a.z += p.z; a.w += p.w;
        }
        *(float4*)(y + o) = a;
    }
}

// ---------------------------------------------------------------------------
// Kernel 4: batched dot. One warp per batch element.
// sum_vec(node) = x0 + (x1+x3) + x2 = emb_input + g_x1 + g_x2
// gamma = dot(su, si) / 16    (folds /(N_LAYERS+1)=/4 on each operand)
// ---------------------------------------------------------------------------
__global__ void __launch_bounds__(256)
dot_kernel(const float* __restrict__ user_emb,
           const float* __restrict__ item_emb,
           const int* __restrict__ users,
           const int* __restrict__ items,
           float* __restrict__ out) {
    int gw   = (blockIdx.x * blockDim.x + threadIdx.x) >> 5;
    int lane = threadIdx.x & 31;
    if (gw >= BATCH_B) return;

    int u  = __ldg(users + gw);
    int it = __ldg(items + gw);

    size_t uo = (size_t)u * D;
    size_t io = (size_t)(NUM_USERS + it) * D;

    float2 su = ((const float2*)(user_emb + uo))[lane];
    float2 t1 = ((const float2*)(g_x1 + uo))[lane];
    float2 t2 = ((const float2*)(g_x2 + uo))[lane];
    su.x += t1.x + t2.x;
    su.y += t1.y + t2.y;

    float2 si = ((const float2*)(item_emb + (size_t)it * D))[lane];
    float2 s1 = ((const float2*)(g_x1 + io))[lane];
    float2 s2 = ((const float2*)(g_x2 + io))[lane];
    si.x += s1.x + s2.x;
    si.y += s1.y + s2.y;

    float s = su.x * si.x + su.y * si.y;
    #pragma unroll
    for (int o = 16; o; o >>= 1) s += __shfl_xor_sync(0xffffffffu, s, o);
    if (lane == 0) out[gw] = s * (1.0f / 16.0f);
}

// ---------------------------------------------------------------------------
// Launch — kernel launches ONLY (graph-capture safe)
// ---------------------------------------------------------------------------
extern "C" void kernel_launch(void* const* d_in, const int* in_sizes, int n_in,
                              void* d_out, int out_size) {
    const float* user_emb  = (const float*)d_in[0];
    const float* item_emb  = (const float*)d_in[1];
    const int*   edge_rows = (const int*)  d_in[2];
    const int*   edge_cols = (const int*)  d_in[3];
    const float* edge_vals = (const float*)d_in[4];
    const int*   users     = (const int*)  d_in[5];
    const int*   items     = (const int*)  d_in[6];
    float*       out       = (float*)d_out;

    {
        int total4 = NUM_NODES * D / 4;
        init_kernel<<<(total4 + 255) / 256, 256>>>(user_emb, item_emb);
    }
    rowptr_kernel<<<(NUM_NODES + 1 + 255) / 256, 256>>>(edge_rows);
    {
        int blk = (NUM_NODES * 32 + 255) / 256;   // 18750 blocks, 8 warps each
        spmm_kernel<0, 1, 0><<<blk, 256>>>(edge_cols, edge_vals);  // x0 -> x1
        spmm_kernel<1, 2, 0><<<blk, 256>>>(edge_cols, edge_vals);  // x1 -> x2
        spmm_kernel<2, 1, 1><<<blk, 256>>>(edge_cols, edge_vals);  // x2 -> x1 (+= x1: holds x1+x3)
    }
    dot_kernel<<<(BATCH_B * 32 + 255) / 256, 256>>>(user_emb, item_emb, users, items, out);
}

// round 6
// speedup vs baseline: 1.3471x; 1.3471x over previous
#include <cuda_runtime.h>
#include <cuda_fp16.h>

#define NUM_USERS 50000
#define NUM_ITEMS 100000
#define NUM_NODES 150000
#define D 64
#define NNZ_E 4800000
#define BATCH_B 4096

// Static scratch (BSS __device__ globals; no allocation anywhere).
// Feature buffers are fp16 to halve L2 gather traffic (the measured bound).
//   layer1: g_x0 -> g_x1 (x1)
//   layer2: g_x1 -> g_x2 (x2)
//   layer3: g_x2 -> g_x1 += (g_x1 ends as x1+x3)
__device__ __half g_x0[(size_t)NUM_NODES * D];
__device__ __half g_x1[(size_t)NUM_NODES * D];
__device__ __half g_x2[(size_t)NUM_NODES * D];
__device__ int    g_rowptr[NUM_NODES + 1];

// ---------------------------------------------------------------------------
// Kernel 1: concat + fp16-quantize embeddings into g_x0.
// Each thread handles 4 floats -> 4 halves (uint2 store, 8B).
// NUM_USERS*D = 3.2M, divisible by 4 -> no straddle.
// ---------------------------------------------------------------------------
__global__ void init_kernel(const float* __restrict__ user_emb,
                            const float* __restrict__ item_emb) {
    int i = blockIdx.x * blockDim.x + threadIdx.x;        // group-of-4 index
    const int total4 = NUM_NODES * D / 4;                  // 2.4M
    if (i >= total4) return;
    const int user4 = NUM_USERS * D / 4;                   // 800k
    float4 v;
    if (i < user4) {
        v = *(const float4*)(user_emb + (size_t)i * 4);
    } else {
        v = *(const float4*)(item_emb + (size_t)(i - user4) * 4);
    }
    __half2 lo = __floats2half2_rn(v.x, v.y);
    __half2 hi = __floats2half2_rn(v.z, v.w);
    uint2 pk;
    pk.x = *(unsigned int*)&lo;
    pk.y = *(unsigned int*)&hi;
    ((uint2*)g_x0)[i] = pk;
}

// ---------------------------------------------------------------------------
// Kernel 2: CSR row pointers via binary search over sorted edge_rows
// ---------------------------------------------------------------------------
__global__ void rowptr_kernel(const int* __restrict__ edge_rows) {
    int r = blockIdx.x * blockDim.x + threadIdx.x;
    if (r > NUM_NODES) return;
    int lo = 0, hi = NNZ_E;
    while (lo < hi) {
        int mid = (lo + hi) >> 1;
        if (__ldg(edge_rows + mid) < r) lo = mid + 1;
        else hi = mid;
    }
    g_rowptr[r] = lo;
}

// ---------------------------------------------------------------------------
// Kernel 3: SpMM, one warp per row (R0 structure, proven fastest layout).
// Lane owns features 2l,2l+1 as one half2 (4B): per edge the warp does
// 1 LDG.32 (128B row = 1 L1 wavefront) + 2 SHFL, accumulating in fp32.
// Output row stored as half2 (round-to-nearest). ADD=1 fuses += into DST.
// ---------------------------------------------------------------------------
template<int SRC, int DST, int ADD>
__global__ void __launch_bounds__(256)
spmm_kernel(const int*   __restrict__ edge_cols,
            const float* __restrict__ edge_vals) {
    const __half* __restrict__ x = (SRC == 0) ? g_x0 : ((SRC == 1) ? g_x1 : g_x2);
    __half*       __restrict__ y = (DST == 1) ? g_x1 : g_x2;

    int gw   = (blockIdx.x * blockDim.x + threadIdx.x) >> 5;
    int lane = threadIdx.x & 31;
    if (gw >= NUM_NODES) return;

    int beg = g_rowptr[gw];
    int end = g_rowptr[gw + 1];
    const int fo = lane * 2;                 // this lane's feature offset

    float2 a = make_float2(0.f, 0.f);

    int e = beg;
    for (; e + 32 <= end; e += 32) {
        int   c = __ldg(edge_cols + e + lane);
        float v = __ldg(edge_vals + e + lane);
        #pragma unroll
        for (int j = 0; j < 32; j++) {
            int   cj = __shfl_sync(0xffffffffu, c, j);
            float vj = __shfl_sync(0xffffffffu, v, j);
            __half2 hv = *(const __half2*)(x + (size_t)cj * D + fo);
            float2 xv = __half22float2(hv);
            a.x = fmaf(vj, xv.x, a.x);
            a.y = fmaf(vj, xv.y, a.y);
        }
    }
    int n = end - e;
    if (n > 0) {
        int   c = 0; float v = 0.f;
        if (lane < n) { c = __ldg(edge_cols + e + lane); v = __ldg(edge_vals + e + lane); }
        for (int j = 0; j < n; j++) {
            int   cj = __shfl_sync(0xffffffffu, c, j);
            float vj = __shfl_sync(0xffffffffu, v, j);
            __half2 hv = *(const __half2*)(x + (size_t)cj * D + fo);
            float2 xv = __half22float2(hv);
            a.x = fmaf(vj, xv.x, a.x);
            a.y = fmaf(vj, xv.y, a.y);
        }
    }

    size_t o = (size_t)gw * D + fo;
    if (ADD) {
        float2 p = __half22float2(*(const __half2*)(y + o));
        a.x += p.x;
        a.y += p.y;
    }
    *(__half2*)(y + o) = __floats2half2_rn(a.x, a.y);
}

// ---------------------------------------------------------------------------
// Kernel 4: batched dot. One warp per batch element.
// sum_vec = x0(fp32 inputs) + (x1+x3)(g_x1) + x2(g_x2); gamma = dot/16.
// ---------------------------------------------------------------------------
__global__ void __launch_bounds__(256)
dot_kernel(const float* __restrict__ user_emb,
           const float* __restrict__ item_emb,
           const int* __restrict__ users,
           const int* __restrict__ items,
           float* __restrict__ out) {
    int gw   = (blockIdx.x * blockDim.x + threadIdx.x) >> 5;
    int lane = threadIdx.x & 31;
    if (gw >= BATCH_B) return;

    int u  = __ldg(users + gw);
    int it = __ldg(items + gw);

    size_t uo = (size_t)u * D;
    size_t io = (size_t)(NUM_USERS + it) * D;

    float2 su = ((const float2*)(user_emb + uo))[lane];
    float2 a1 = __half22float2(((const __half2*)(g_x1 + uo))[lane]);
    float2 a2 = __half22float2(((const __half2*)(g_x2 + uo))[lane]);
    su.x += a1.x + a2.x;
    su.y += a1.y + a2.y;

    float2 si = ((const float2*)(item_emb + (size_t)it * D))[lane];
    float2 b1 = __half22float2(((const __half2*)(g_x1 + io))[lane]);
    float2 b2 = __half22float2(((const __half2*)(g_x2 + io))[lane]);
    si.x += b1.x + b2.x;
    si.y += b1.y + b2.y;

    float s = su.x * si.x + su.y * si.y;
    #pragma unroll
    for (int o = 16; o; o >>= 1) s += __shfl_xor_sync(0xffffffffu, s, o);
    if (lane == 0) out[gw] = s * (1.0f / 16.0f);
}

// ---------------------------------------------------------------------------
// Launch — kernel launches ONLY (graph-capture safe)
// ---------------------------------------------------------------------------
extern "C" void kernel_launch(void* const* d_in, const int* in_sizes, int n_in,
                              void* d_out, int out_size) {
    const float* user_emb  = (const float*)d_in[0];
    const float* item_emb  = (const float*)d_in[1];
    const int*   edge_rows = (const int*)  d_in[2];
    const int*   edge_cols = (const int*)  d_in[3];
    const float* edge_vals = (const float*)d_in[4];
    const int*   users     = (const int*)  d_in[5];
    const int*   items     = (const int*)  d_in[6];
    float*       out       = (float*)d_out;

    {
        int total4 = NUM_NODES * D / 4;
        init_kernel<<<(total4 + 255) / 256, 256>>>(user_emb, item_emb);
    }
    rowptr_kernel<<<(NUM_NODES + 1 + 255) / 256, 256>>>(edge_rows);
    {
        int blk = (NUM_NODES * 32 + 255) / 256;   // 18750 blocks, 8 warps each
        spmm_kernel<0, 1, 0><<<blk, 256>>>(edge_cols, edge_vals);  // x0 -> x1
        spmm_kernel<1, 2, 0><<<blk, 256>>>(edge_cols, edge_vals);  // x1 -> x2
        spmm_kernel<2, 1, 1><<<blk, 256>>>(edge_cols, edge_vals);  // x2 -> x1 (x1+x3)
    }
    dot_kernel<<<(BATCH_B * 32 + 255) / 256, 256>>>(user_emb, item_emb, users, items, out);
}